// round 2
// baseline (speedup 1.0000x reference)
#include <cuda_runtime.h>

// EMA along last axis: acc_t = w*x_t + (1-w)*acc_{t-1}
// [B,C,F,T] fp32, T=6000 contiguous. 4112 independent sequences.
//
// One CTA per sequence. NO smem data staging: each thread loads its
// 12-element chunk directly (3x float4, streaming), scans in registers,
// couples chunks via a shuffle-based affine scan (constant coeff aL),
// then stores directly (3x float4, streaming). Only 2 barriers.

constexpr int T_LEN = 6000;
constexpr int NT    = 512;
constexpr int L     = 12;           // chunk per thread
constexpr int NCH   = T_LEN / L;    // 500 active threads
constexpr int NW    = NT / 32;      // 16 warps

__global__ __launch_bounds__(NT, 3)
void ema_kernel(const float* __restrict__ x,
                const float* __restrict__ init,
                const float* __restrict__ wptr,
                float* __restrict__ out)
{
    __shared__ float wsum[NW];   // cross-warp carry scan (64 B)

    const int seq  = blockIdx.x;
    const int t    = threadIdx.x;
    const int lane = t & 31;
    const int wid  = t >> 5;

    float w = fminf(fmaxf(wptr[0], 0.0f), 1.0f);
    const float a = 1.0f - w;

    // a^L
    float aL = 1.0f;
    #pragma unroll
    for (int k = 0; k < L; k++) aL *= a;

    const bool active = (t < NCH);

    // ---- 1. direct load (3x float4, streaming) + local scan, zero init ----
    float local[L];
    float acc = 0.0f;
    if (active) {
        const float4* x4 = reinterpret_cast<const float4*>(x + (size_t)seq * T_LEN) + t * 3;
        float4 v0 = __ldcs(x4 + 0);
        float4 v1 = __ldcs(x4 + 1);
        float4 v2 = __ldcs(x4 + 2);
        float xv[L] = { v0.x, v0.y, v0.z, v0.w,
                        v1.x, v1.y, v1.z, v1.w,
                        v2.x, v2.y, v2.z, v2.w };
        #pragma unroll
        for (int k = 0; k < L; k++) {
            acc = fmaf(w, xv[k], a * acc);
            local[k] = acc;
        }
    }
    float e = active ? acc : 0.0f;

    // ---- 2. warp-level inclusive affine scan: D_t = e_t + aL * D_{t-1} ----
    float D  = e;
    float sc = aL;                       // aL^(2^s)
    #pragma unroll
    for (int s = 1; s < 32; s <<= 1) {
        float p = __shfl_up_sync(0xffffffffu, D, s);
        if (lane >= s) D = fmaf(sc, p, D);
        sc *= sc;
    }
    const float aL32 = sc;               // aL^32 after 5 doublings

    if (lane == 31) wsum[wid] = D;
    __syncthreads();

    // ---- 3. warp 0 scans the 16 warp totals (coeff aL^32) ----
    if (wid == 0) {
        float v = (lane < NW) ? wsum[lane] : 0.0f;
        float sc2 = aL32;
        #pragma unroll
        for (int s = 1; s < NW; s <<= 1) {
            float p = __shfl_up_sync(0xffffffffu, v, s);
            if (lane >= s) v = fmaf(sc2, p, v);
            sc2 *= sc2;
        }
        if (lane < NW) wsum[lane] = v;
    }
    __syncthreads();

    // ---- 4. incoming state for this chunk:
    //         Dex_full = (exclusive warp scan) + aL^lane * S_{wid-1}
    //         C = aL^t * init + Dex_full ----
    float Sprev = (wid > 0) ? wsum[wid - 1] : 0.0f;
    float Dex = __shfl_up_sync(0xffffffffu, D, 1);
    if (lane == 0) Dex = 0.0f;
    float DexF = fmaf(powf(aL, (float)lane), Sprev, Dex);
    float C    = fmaf(powf(aL, (float)t), init[seq], DexF);

    // ---- 5. y_k = local_k + a^(k+1) * C ; direct streaming store ----
    if (active) {
        float y[L];
        float pw = a;
        #pragma unroll
        for (int k = 0; k < L; k++) {
            y[k] = fmaf(pw, C, local[k]);
            pw *= a;
        }
        float4* o4 = reinterpret_cast<float4*>(out + (size_t)seq * T_LEN) + t * 3;
        __stcs(o4 + 0, make_float4(y[0], y[1], y[2],  y[3]));
        __stcs(o4 + 1, make_float4(y[4], y[5], y[6],  y[7]));
        __stcs(o4 + 2, make_float4(y[8], y[9], y[10], y[11]));
    }
}

extern "C" void kernel_launch(void* const* d_in, const int* in_sizes, int n_in,
                              void* d_out, int out_size)
{
    const float* x    = (const float*)d_in[0];   // mag_spec  [B,C,F,T]
    const float* init = (const float*)d_in[1];   // initial_state [B,C,F,1]
    const float* wp   = (const float*)d_in[2];   // weights [1]
    float*       out  = (float*)d_out;

    const int nseq = in_sizes[1];                // B*C*F = 4112
    ema_kernel<<<nseq, NT>>>(x, init, wp, out);
}

// round 3
// speedup vs baseline: 1.1347x; 1.1347x over previous
#include <cuda_runtime.h>

// EMA along last axis: acc_t = w*x_t + (1-w)*acc_{t-1}
// [B,C,F,T] fp32, T=6000 contiguous; 4112 independent sequences.
//
// One WARP per sequence, walking time in 128-element segments.
// Lane k owns times 4k..4k+3 of the segment -> every LDG.128/STG.128 is a
// dense 512B transaction. Cross-lane coupling via 5-step shuffle affine
// scan (constant coeff a^4). Carry chains in a register across segments.
// Zero shared memory, zero barriers, 2-segment load prefetch for MLP.

constexpr int T_LEN     = 6000;
constexpr int SEG       = 128;                // 32 lanes x 4 floats
constexpr int NFULL     = T_LEN / SEG;        // 46
constexpr int REM       = T_LEN - NFULL*SEG;  // 112
constexpr int REM_LANES = REM / 4;            // 28
constexpr int WPB       = 8;                  // warps per block

__global__ __launch_bounds__(WPB * 32)
void ema_kernel(const float* __restrict__ x,
                const float* __restrict__ init,
                const float* __restrict__ wptr,
                float* __restrict__ out,
                int nseq)
{
    const int lane = threadIdx.x & 31;
    const int wid  = threadIdx.x >> 5;
    const int seq  = blockIdx.x * WPB + wid;
    if (seq >= nseq) return;                  // warp-uniform exit

    const float w  = fminf(fmaxf(wptr[0], 0.0f), 1.0f);
    const float a  = 1.0f - w;
    const float a2 = a * a;
    const float a3 = a2 * a;
    const float a4 = a2 * a2;
    const float alane = powf(a4, (float)lane);  // a^(4*lane), once per warp
    const float a128  = powf(a4, 32.0f);        // a^128

    const float4* xp = reinterpret_cast<const float4*>(x + (size_t)seq * T_LEN);
    float4*       op = reinterpret_cast<float4*>(out + (size_t)seq * T_LEN);

    float carry = init[seq];                  // running state entering segment

    // one segment = dense 512B: lane k -> float4 index (seg*32 + k)
    auto process = [&](float4 c, int segi, bool store_ok) {
        float local0 = fmaf(w, c.x, a * 0.0f);
        float local1 = fmaf(w, c.y, a * local0);
        float local2 = fmaf(w, c.z, a * local1);
        float local3 = fmaf(w, c.w, a * local2);

        // inclusive affine scan over lanes: D_l = e_l + a4 * D_{l-1}
        float D  = local3;
        float sc = a4;
        #pragma unroll
        for (int s = 1; s < 32; s <<= 1) {
            float p = __shfl_up_sync(0xffffffffu, D, s);
            if (lane >= s) D = fmaf(sc, p, D);
            sc *= sc;
        }
        float Dex = __shfl_up_sync(0xffffffffu, D, 1);
        if (lane == 0) Dex = 0.0f;
        float C   = fmaf(alane, carry, Dex);      // incoming state for this lane
        float D31 = __shfl_sync(0xffffffffu, D, 31);
        carry = fmaf(a128, carry, D31);           // state entering next segment

        if (store_ok) {
            float4 y = make_float4(fmaf(a,  C, local0),
                                   fmaf(a2, C, local1),
                                   fmaf(a3, C, local2),
                                   fmaf(a4, C, local3));
            __stcs(op + segi * 32 + lane, y);
        }
    };

    // prefetch segments 0 and 1
    float4 b0 = __ldcs(xp + 0 * 32 + lane);
    float4 b1 = __ldcs(xp + 1 * 32 + lane);

    #pragma unroll 1
    for (int i = 0; i < NFULL; i += 2) {       // 46 full segments, 2 per iter
        float4 c0 = b0, c1 = b1;
        // prefetch i+2 and i+3 (independent of carry)
        int j0 = i + 2;
        if (j0 < NFULL) {
            b0 = __ldcs(xp + j0 * 32 + lane);
        } else if (lane < REM_LANES) {         // j0 == NFULL -> tail segment
            b0 = __ldcs(xp + NFULL * 32 + lane);
        } else {
            b0 = make_float4(0.f, 0.f, 0.f, 0.f);
        }
        int j1 = i + 3;
        if (j1 < NFULL) {
            b1 = __ldcs(xp + j1 * 32 + lane);
        }
        process(c0, i,     true);
        process(c1, i + 1, true);
    }

    // tail: 112 elements (28 lanes x 4), data already in b0
    process(b0, NFULL, lane < REM_LANES);
}

extern "C" void kernel_launch(void* const* d_in, const int* in_sizes, int n_in,
                              void* d_out, int out_size)
{
    const float* x    = (const float*)d_in[0];   // mag_spec  [B,C,F,T]
    const float* init = (const float*)d_in[1];   // initial_state [B,C,F,1]
    const float* wp   = (const float*)d_in[2];   // weights [1]
    float*       out  = (float*)d_out;

    const int nseq = in_sizes[1];                // B*C*F = 4112
    const int blocks = (nseq + WPB - 1) / WPB;   // 514
    ema_kernel<<<blocks, WPB * 32>>>(x, init, wp, out, nseq);
}

// round 4
// speedup vs baseline: 1.1356x; 1.0008x over previous
#include <cuda_runtime.h>

// EMA along last axis: acc_t = w*x_t + (1-w)*acc_{t-1}
// [B,C,F,T] fp32, T=6000 contiguous; 4112 independent sequences.
//
// One WARP per sequence, 128-element segments (lane k owns times 4k..4k+3:
// every LDG.128/STG.128 is a dense 512B transaction). Cross-lane coupling
// via 5-step shuffle affine scan (coeff a^4). Carry chains in a register.
// Zero smem/barriers. 4-segment-deep load prefetch (2KB in flight per warp)
// with loads issued ahead of the serial scan chain.

constexpr int T_LEN     = 6000;
constexpr int SEG       = 128;                // 32 lanes x 4 floats
constexpr int NFULL     = T_LEN / SEG;        // 46
constexpr int REM       = T_LEN - NFULL*SEG;  // 112
constexpr int REM_LANES = REM / 4;            // 28
constexpr int WPB       = 4;                  // warps per block (small -> smooth waves)

__global__ __launch_bounds__(WPB * 32)
void ema_kernel(const float* __restrict__ x,
                const float* __restrict__ init,
                const float* __restrict__ wptr,
                float* __restrict__ out,
                int nseq)
{
    const int lane = threadIdx.x & 31;
    const int wid  = threadIdx.x >> 5;
    const int seq  = blockIdx.x * WPB + wid;
    if (seq >= nseq) return;                  // warp-uniform exit

    const float w  = fminf(fmaxf(wptr[0], 0.0f), 1.0f);
    const float a  = 1.0f - w;
    const float a2 = a * a;
    const float a3 = a2 * a;
    const float a4 = a2 * a2;
    const float alane = powf(a4, (float)lane);  // a^(4*lane)
    const float a128  = powf(a4, 32.0f);        // a^128

    const float4* xp = reinterpret_cast<const float4*>(x + (size_t)seq * T_LEN);
    float4*       op = reinterpret_cast<float4*>(out + (size_t)seq * T_LEN);

    float carry = init[seq];                  // state entering current segment

    // predicated dense segment load (seg j; j==NFULL is the 112-elem tail)
    auto load_seg = [&](int j) -> float4 {
        if (j < NFULL)                     return __ldcs(xp + j * 32 + lane);
        if (j == NFULL && lane < REM_LANES) return __ldcs(xp + j * 32 + lane);
        return make_float4(0.f, 0.f, 0.f, 0.f);
    };

    auto process = [&](float4 c, int segi, bool store_ok) {
        float local0 = w * c.x;
        float local1 = fmaf(w, c.y, a * local0);
        float local2 = fmaf(w, c.z, a * local1);
        float local3 = fmaf(w, c.w, a * local2);

        // inclusive affine scan over lanes: D_l = e_l + a4 * D_{l-1}
        float D  = local3;
        float sc = a4;
        #pragma unroll
        for (int s = 1; s < 32; s <<= 1) {
            float p = __shfl_up_sync(0xffffffffu, D, s);
            if (lane >= s) D = fmaf(sc, p, D);
            sc *= sc;
        }
        float Dex = __shfl_up_sync(0xffffffffu, D, 1);
        if (lane == 0) Dex = 0.0f;
        float C   = fmaf(alane, carry, Dex);      // incoming state, this lane
        float D31 = __shfl_sync(0xffffffffu, D, 31);
        carry = fmaf(a128, carry, D31);           // state entering next segment

        if (store_ok) {
            float4 y = make_float4(fmaf(a,  C, local0),
                                   fmaf(a2, C, local1),
                                   fmaf(a3, C, local2),
                                   fmaf(a4, C, local3));
            __stcs(op + segi * 32 + lane, y);
        }
    };

    // 4-deep prefetch: b0..b3 hold segments i..i+3
    float4 b0 = load_seg(0);
    float4 b1 = load_seg(1);
    float4 b2 = load_seg(2);
    float4 b3 = load_seg(3);

    #pragma unroll 1
    for (int i = 0; i < NFULL; i += 2) {       // 23 iterations
        float4 c0 = b0, c1 = b1;
        b0 = b2; b1 = b3;
        // issue next loads BEFORE the serial scan chain
        b2 = load_seg(i + 4);
        b3 = load_seg(i + 5);
        process(c0, i,     true);
        process(c1, i + 1, true);
    }

    // tail segment 46 (112 elems) is sitting in b0 after the final shift
    process(b0, NFULL, lane < REM_LANES);
}

extern "C" void kernel_launch(void* const* d_in, const int* in_sizes, int n_in,
                              void* d_out, int out_size)
{
    const float* x    = (const float*)d_in[0];   // mag_spec  [B,C,F,T]
    const float* init = (const float*)d_in[1];   // initial_state [B,C,F,1]
    const float* wp   = (const float*)d_in[2];   // weights [1]
    float*       out  = (float*)d_out;

    const int nseq = in_sizes[1];                // B*C*F = 4112
    const int blocks = (nseq + WPB - 1) / WPB;   // 1028
    ema_kernel<<<blocks, WPB * 32>>>(x, init, wp, out, nseq);
}